// round 2
// baseline (speedup 1.0000x reference)
#include <cuda_runtime.h>
#include <cuda_bf16.h>
#include <cstdint>

// Problem constants (shapes are fixed by the dataset).
#define NN 100000
#define EE 1600000
#define HD 64

// ---------------- scratch (device globals: allocation-free) ----------------
__device__ int   g_is64;
__device__ int   g_src32[EE];
__device__ int   g_dst32[EE];
__device__ int   g_cnt[NN];
__device__ int   g_rowstart[NN + 1];
__device__ int   g_cursor[NN];
__device__ float g_dis[NN];
__device__ int   g_csrc[EE];
__device__ float g_cw[EE];
__device__ float g_bufA[(size_t)NN * HD];
__device__ float g_bufB[(size_t)NN * HD];

// ---------------- dtype sniff: int64 edge_index has zero high words ----------------
__global__ void k_detect(const void* ei) {
    __shared__ int nz;
    if (threadIdx.x == 0) nz = 0;
    __syncthreads();
    // Interpret as uint32 pairs: for int64 data (values < 2^31) every odd word is 0.
    // For int32 data, odd words are random node ids (virtually never all zero).
    unsigned v = ((const unsigned*)ei)[2 * threadIdx.x + 1];
    if (v != 0) atomicOr(&nz, 1);
    __syncthreads();
    if (threadIdx.x == 0) g_is64 = (nz == 0) ? 1 : 0;
}

// ---------------- convert edge_index to int32 src/dst ----------------
__global__ void k_convert(const void* ei, int e) {
    int i = blockIdx.x * blockDim.x + threadIdx.x;
    if (i >= e) return;
    int s, d;
    if (g_is64) {
        const long long* p = (const long long*)ei;
        s = (int)p[i];
        d = (int)p[(size_t)e + i];
    } else {
        const int* p = (const int*)ei;
        s = p[i];
        d = p[e + i];
    }
    g_src32[i] = s;
    g_dst32[i] = d;
}

// ---------------- prep kernels ----------------
__global__ void k_zero_int(int* p, int n) {
    int i = blockIdx.x * blockDim.x + threadIdx.x;
    if (i < n) p[i] = 0;
}

__global__ void k_hist(const int* __restrict__ dst, int e, int* __restrict__ cnt, int n) {
    int i = blockIdx.x * blockDim.x + threadIdx.x;
    if (i < e) {
        int d = dst[i];
        if ((unsigned)d < (unsigned)n) atomicAdd(&cnt[d], 1);
    }
}

__global__ void k_dis(const int* __restrict__ cnt, float* __restrict__ dis, int n) {
    int i = blockIdx.x * blockDim.x + threadIdx.x;
    if (i < n) dis[i] = rsqrtf((float)cnt[i] + 1.0f);
}

// Single-block Hillis-Steele scan over chunks of 1024. n=100k -> ~98 chunks, cheap.
__global__ void k_scan(const int* __restrict__ cnt, int* __restrict__ rowstart,
                       int* __restrict__ cursor, int n) {
    __shared__ int sh[1024];
    int t = threadIdx.x;
    int carry = 0;
    for (int base = 0; base < n; base += 1024) {
        int i = base + t;
        int v = (i < n) ? cnt[i] : 0;
        sh[t] = v;
        __syncthreads();
        #pragma unroll
        for (int off = 1; off < 1024; off <<= 1) {
            int add = (t >= off) ? sh[t - off] : 0;
            __syncthreads();
            sh[t] += add;
            __syncthreads();
        }
        int excl = carry + sh[t] - v;
        if (i < n) { rowstart[i] = excl; cursor[i] = excl; }
        carry += sh[1023];   // sh fully scanned; read before next chunk overwrites
        __syncthreads();
    }
    if (t == 0) rowstart[n] = carry;
}

__global__ void k_fill(const int* __restrict__ src, const int* __restrict__ dst,
                       int e, int n, const float* __restrict__ dis,
                       int* __restrict__ cursor, int* __restrict__ csrc, float* __restrict__ cw) {
    int i = blockIdx.x * blockDim.x + threadIdx.x;
    if (i < e) {
        int s = src[i];
        int d = dst[i];
        if ((unsigned)s >= (unsigned)n || (unsigned)d >= (unsigned)n) return;
        float w = dis[s] * dis[d];
        int p = atomicAdd(&cursor[d], 1);
        csrc[p] = s;
        cw[p]   = w;
    }
}

// ---------------- GEMM: Y[n,64] = act(X)[n,64] @ W[64,64] ----------------
// 256 threads, 64-row tile, 4x4 micro-tile per thread. ReLU fused on input load.
__global__ void __launch_bounds__(256) k_gemm(const float* __restrict__ X,
                                              const float* __restrict__ W,
                                              float* __restrict__ Y, int n, int relu_in) {
    __shared__ float sW[64 * 64];
    __shared__ float sX[64 * 68];   // pad 68 to avoid a-load bank conflicts

    int t    = threadIdx.x;
    int row0 = blockIdx.x * 64;

    // Load W (4096 floats) via float4, coalesced.
    {
        const float4* W4  = (const float4*)W;
        float4*       sW4 = (float4*)sW;
        #pragma unroll
        for (int i = 0; i < 4; i++) sW4[t + i * 256] = W4[t + i * 256];
    }
    // Load X tile (64 rows x 64 cols) with optional ReLU, zero-pad OOB rows.
    {
        int kc = (t & 15) * 4;
        int rl = t >> 4;            // 0..15
        #pragma unroll
        for (int i = 0; i < 4; i++) {
            int r  = rl + i * 16;
            int gr = row0 + r;
            float4 v = make_float4(0.f, 0.f, 0.f, 0.f);
            if (gr < n) v = *(const float4*)&X[(size_t)gr * HD + kc];
            if (relu_in) {
                v.x = fmaxf(v.x, 0.f); v.y = fmaxf(v.y, 0.f);
                v.z = fmaxf(v.z, 0.f); v.w = fmaxf(v.w, 0.f);
            }
            *(float4*)&sX[r * 68 + kc] = v;
        }
    }
    __syncthreads();

    int tx = t & 15, ty = t >> 4;
    int r0 = ty * 4, j0 = tx * 4;

    float acc[4][4];
    #pragma unroll
    for (int r = 0; r < 4; r++)
        #pragma unroll
        for (int c = 0; c < 4; c++) acc[r][c] = 0.f;

    #pragma unroll 4
    for (int k = 0; k < 64; k += 4) {
        float a[4][4];
        #pragma unroll
        for (int r = 0; r < 4; r++) {
            float4 t4 = *(const float4*)&sX[(r0 + r) * 68 + k];
            a[r][0] = t4.x; a[r][1] = t4.y; a[r][2] = t4.z; a[r][3] = t4.w;
        }
        #pragma unroll
        for (int kk = 0; kk < 4; kk++) {
            float4 w4 = *(const float4*)&sW[(k + kk) * 64 + j0];
            float wv[4] = {w4.x, w4.y, w4.z, w4.w};
            #pragma unroll
            for (int r = 0; r < 4; r++)
                #pragma unroll
                for (int c = 0; c < 4; c++)
                    acc[r][c] = fmaf(a[r][kk], wv[c], acc[r][c]);
        }
    }

    #pragma unroll
    for (int r = 0; r < 4; r++) {
        int gr = row0 + r0 + r;
        if (gr < n)
            *(float4*)&Y[(size_t)gr * HD + j0] =
                make_float4(acc[r][0], acc[r][1], acc[r][2], acc[r][3]);
    }
}

// ---------------- Gather: one warp per dst node ----------------
// Y[i] = sum_{e in CSR(i)} A[src_e]*w_e  +  A[i]*dis[i]^2  +  b
__global__ void __launch_bounds__(256) k_gather(const float* __restrict__ A,
                                                const int* __restrict__ rowstart,
                                                const int* __restrict__ csrc,
                                                const float* __restrict__ cw,
                                                const float* __restrict__ dis,
                                                const float* __restrict__ bias,
                                                float* __restrict__ Y, int n) {
    int wid  = (blockIdx.x * blockDim.x + threadIdx.x) >> 5;
    int lane = threadIdx.x & 31;
    if (wid >= n) return;

    float d  = dis[wid];
    float sn = d * d;
    float2 a = *(const float2*)&A[(size_t)wid * HD + lane * 2];
    float2 acc;
    acc.x = a.x * sn;
    acc.y = a.y * sn;

    int e0 = rowstart[wid];
    int e1 = rowstart[wid + 1];
    for (int e = e0; e < e1; e++) {
        int   s = csrc[e];   // warp-uniform broadcast load
        float w = cw[e];
        float2 v = *(const float2*)&A[(size_t)s * HD + lane * 2];
        acc.x = fmaf(v.x, w, acc.x);
        acc.y = fmaf(v.y, w, acc.y);
    }

    float2 b = *(const float2*)&bias[lane * 2];
    acc.x += b.x;
    acc.y += b.y;
    *(float2*)&Y[(size_t)wid * HD + lane * 2] = acc;
}

// ---------------- launch ----------------
extern "C" void kernel_launch(void* const* d_in, const int* in_sizes, int n_in,
                              void* d_out, int out_size) {
    const float* x  = (const float*)d_in[0];
    const void*  ei = d_in[1];   // [2,E]; dtype sniffed on device (int32 vs int64)
    // d_in[2] = edge_features, unused by GCNConv
    const float* W1 = (const float*)d_in[3];
    const float* b1 = (const float*)d_in[4];
    const float* W2 = (const float*)d_in[5];
    const float* b2 = (const float*)d_in[6];
    const float* W3 = (const float*)d_in[7];
    const float* b3 = (const float*)d_in[8];

    int n = in_sizes[0] / HD;   // 100000
    int e = in_sizes[1] / 2;    // 1600000

    int*   src32;    cudaGetSymbolAddress((void**)&src32, g_src32);
    int*   dst32;    cudaGetSymbolAddress((void**)&dst32, g_dst32);
    int*   cnt;      cudaGetSymbolAddress((void**)&cnt, g_cnt);
    int*   rowstart; cudaGetSymbolAddress((void**)&rowstart, g_rowstart);
    int*   cursor;   cudaGetSymbolAddress((void**)&cursor, g_cursor);
    float* dis;      cudaGetSymbolAddress((void**)&dis, g_dis);
    int*   csrc;     cudaGetSymbolAddress((void**)&csrc, g_csrc);
    float* cw;       cudaGetSymbolAddress((void**)&cw, g_cw);
    float* bufA;     cudaGetSymbolAddress((void**)&bufA, g_bufA);
    float* bufB;     cudaGetSymbolAddress((void**)&bufB, g_bufB);
    float* out = (float*)d_out;

    int nb_n = (n + 255) / 256;
    int nb_e = (e + 255) / 256;
    int nb_g = (n * 32 + 255) / 256;   // one warp per node
    int nb_m = (n + 63) / 64;

    // ---- edge index normalization + CSR build (once per call) ----
    k_detect<<<1, 256>>>(ei);
    k_convert<<<nb_e, 256>>>(ei, e);
    k_zero_int<<<nb_n, 256>>>(cnt, n);
    k_hist<<<nb_e, 256>>>(dst32, e, cnt, n);
    k_scan<<<1, 1024>>>(cnt, rowstart, cursor, n);
    k_dis<<<nb_n, 256>>>(cnt, dis, n);
    k_fill<<<nb_e, 256>>>(src32, dst32, e, n, dis, cursor, csrc, cw);

    // ---- layer 1 ----
    k_gemm<<<nb_m, 256>>>(x, W1, bufA, n, 0);
    k_gather<<<nb_g, 256>>>(bufA, rowstart, csrc, cw, dis, b1, bufB, n);
    // ---- layer 2 (ReLU fused into GEMM input load) ----
    k_gemm<<<nb_m, 256>>>(bufB, W2, bufA, n, 1);
    k_gather<<<nb_g, 256>>>(bufA, rowstart, csrc, cw, dis, b2, bufB, n);
    // ---- layer 3 ----
    k_gemm<<<nb_m, 256>>>(bufB, W3, bufA, n, 1);
    k_gather<<<nb_g, 256>>>(bufA, rowstart, csrc, cw, dis, b3, out, n);
}

// round 4
// speedup vs baseline: 1.5648x; 1.5648x over previous
#include <cuda_runtime.h>
#include <cuda_bf16.h>
#include <cstdint>

// Problem constants (shapes are fixed by the dataset).
#define NN 100000
#define EE 1600000
#define HD 64
#define SCAN_CHUNK 1024
#define MAX_SCAN_BLOCKS 128

// ---------------- scratch (device globals: allocation-free) ----------------
__device__ int   g_is64;
__device__ int   g_src32[EE];
__device__ int   g_dst32[EE];
__device__ int   g_cnt[NN];
__device__ int   g_rowstart[NN + 1];
__device__ int   g_cursor[NN];
__device__ float g_dis[NN];
__device__ int   g_blocksum[MAX_SCAN_BLOCKS];
__device__ int   g_blockoff[MAX_SCAN_BLOCKS];
__device__ int   g_csrc[EE];
__device__ float g_cw[EE];
__device__ float g_bufA[(size_t)NN * HD];
__device__ float g_bufB[(size_t)NN * HD];

// ---------------- dtype sniff: int64 edge_index has zero high words ----------------
__global__ void k_detect(const void* ei) {
    __shared__ int nz;
    if (threadIdx.x == 0) nz = 0;
    __syncthreads();
    unsigned v = ((const unsigned*)ei)[2 * threadIdx.x + 1];
    if (v != 0) atomicOr(&nz, 1);
    __syncthreads();
    if (threadIdx.x == 0) g_is64 = (nz == 0) ? 1 : 0;
}

__global__ void k_zero_int(int* p, int n) {
    int i = blockIdx.x * blockDim.x + threadIdx.x;
    if (i < n) p[i] = 0;
}

// ---------------- convert edge_index to int32 src/dst AND histogram dst ----------------
__global__ void k_convhist(const void* ei, int e, int n, int* __restrict__ cnt) {
    int i = blockIdx.x * blockDim.x + threadIdx.x;
    if (i >= e) return;
    int s, d;
    if (g_is64) {
        const long long* p = (const long long*)ei;
        s = (int)p[i];
        d = (int)p[(size_t)e + i];
    } else {
        const int* p = (const int*)ei;
        s = p[i];
        d = p[e + i];
    }
    g_src32[i] = s;
    g_dst32[i] = d;
    if ((unsigned)d < (unsigned)n) atomicAdd(&cnt[d], 1);
}

// ---------------- 3-phase parallel scan over cnt ----------------
// Phase 1: per-block (1024-wide) inclusive scan; write local-exclusive, blocksum, dis.
__global__ void __launch_bounds__(SCAN_CHUNK) k_scan1(const int* __restrict__ cnt,
                                                      int* __restrict__ rowstart,
                                                      int* __restrict__ blocksum,
                                                      float* __restrict__ dis, int n) {
    __shared__ int sh[SCAN_CHUNK];
    int t = threadIdx.x;
    int i = blockIdx.x * SCAN_CHUNK + t;
    int v = (i < n) ? cnt[i] : 0;
    if (i < n) dis[i] = rsqrtf((float)v + 1.0f);
    sh[t] = v;
    __syncthreads();
    #pragma unroll
    for (int off = 1; off < SCAN_CHUNK; off <<= 1) {
        int add = (t >= off) ? sh[t - off] : 0;
        __syncthreads();
        sh[t] += add;
        __syncthreads();
    }
    if (i < n) rowstart[i] = sh[t] - v;            // local exclusive prefix
    if (t == SCAN_CHUNK - 1) blocksum[blockIdx.x] = sh[SCAN_CHUNK - 1];
}

// Phase 2: one 128-thread block scans the <=128 blocksums (exclusive).
__global__ void k_scan2(const int* __restrict__ blocksum, int* __restrict__ blockoff,
                        int nb, int* __restrict__ rowstart, int n) {
    __shared__ int sh[MAX_SCAN_BLOCKS];
    int t = threadIdx.x;
    int v = (t < nb) ? blocksum[t] : 0;
    sh[t] = v;
    __syncthreads();
    #pragma unroll
    for (int off = 1; off < MAX_SCAN_BLOCKS; off <<= 1) {
        int add = (t >= off) ? sh[t - off] : 0;
        __syncthreads();
        sh[t] += add;
        __syncthreads();
    }
    if (t < nb) blockoff[t] = sh[t] - v;
    if (t == MAX_SCAN_BLOCKS - 1) rowstart[n] = sh[MAX_SCAN_BLOCKS - 1];
}

// Phase 3: add block offsets; init cursor.
__global__ void __launch_bounds__(SCAN_CHUNK) k_scan3(int* __restrict__ rowstart,
                                                      int* __restrict__ cursor,
                                                      const int* __restrict__ blockoff, int n) {
    int i = blockIdx.x * SCAN_CHUNK + threadIdx.x;
    if (i < n) {
        int r = rowstart[i] + blockoff[blockIdx.x];
        rowstart[i] = r;
        cursor[i]   = r;
    }
}

// ---------------- CSR fill ----------------
__global__ void k_fill(const int* __restrict__ src, const int* __restrict__ dst,
                       int e, int n, const float* __restrict__ dis,
                       int* __restrict__ cursor, int* __restrict__ csrc, float* __restrict__ cw) {
    int i = blockIdx.x * blockDim.x + threadIdx.x;
    if (i < e) {
        int s = src[i];
        int d = dst[i];
        if ((unsigned)s >= (unsigned)n || (unsigned)d >= (unsigned)n) return;
        float w = dis[s] * dis[d];
        int p = atomicAdd(&cursor[d], 1);
        csrc[p] = s;
        cw[p]   = w;
    }
}

// ---------------- GEMM: Y[n,64] = act(X)[n,64] @ W[64,64] ----------------
__global__ void __launch_bounds__(256) k_gemm(const float* __restrict__ X,
                                              const float* __restrict__ W,
                                              float* __restrict__ Y, int n, int relu_in) {
    __shared__ float sW[64 * 64];
    __shared__ float sX[64 * 68];

    int t    = threadIdx.x;
    int row0 = blockIdx.x * 64;

    {
        const float4* W4  = (const float4*)W;
        float4*       sW4 = (float4*)sW;
        #pragma unroll
        for (int i = 0; i < 4; i++) sW4[t + i * 256] = W4[t + i * 256];
    }
    {
        int kc = (t & 15) * 4;
        int rl = t >> 4;
        #pragma unroll
        for (int i = 0; i < 4; i++) {
            int r  = rl + i * 16;
            int gr = row0 + r;
            float4 v = make_float4(0.f, 0.f, 0.f, 0.f);
            if (gr < n) v = *(const float4*)&X[(size_t)gr * HD + kc];
            if (relu_in) {
                v.x = fmaxf(v.x, 0.f); v.y = fmaxf(v.y, 0.f);
                v.z = fmaxf(v.z, 0.f); v.w = fmaxf(v.w, 0.f);
            }
            *(float4*)&sX[r * 68 + kc] = v;
        }
    }
    __syncthreads();

    int tx = t & 15, ty = t >> 4;
    int r0 = ty * 4, j0 = tx * 4;

    float acc[4][4];
    #pragma unroll
    for (int r = 0; r < 4; r++)
        #pragma unroll
        for (int c = 0; c < 4; c++) acc[r][c] = 0.f;

    #pragma unroll 4
    for (int k = 0; k < 64; k += 4) {
        float a[4][4];
        #pragma unroll
        for (int r = 0; r < 4; r++) {
            float4 t4 = *(const float4*)&sX[(r0 + r) * 68 + k];
            a[r][0] = t4.x; a[r][1] = t4.y; a[r][2] = t4.z; a[r][3] = t4.w;
        }
        #pragma unroll
        for (int kk = 0; kk < 4; kk++) {
            float4 w4 = *(const float4*)&sW[(k + kk) * 64 + j0];
            float wv[4] = {w4.x, w4.y, w4.z, w4.w};
            #pragma unroll
            for (int r = 0; r < 4; r++)
                #pragma unroll
                for (int c = 0; c < 4; c++)
                    acc[r][c] = fmaf(a[r][kk], wv[c], acc[r][c]);
        }
    }

    #pragma unroll
    for (int r = 0; r < 4; r++) {
        int gr = row0 + r0 + r;
        if (gr < n)
            *(float4*)&Y[(size_t)gr * HD + j0] =
                make_float4(acc[r][0], acc[r][1], acc[r][2], acc[r][3]);
    }
}

// ---------------- Gather: one warp per dst node, edge loop unrolled x4 ----------------
// Y[i] = sum_{e in CSR(i)} A[src_e]*w_e  +  A[i]*dis[i]^2  +  b
__global__ void __launch_bounds__(256) k_gather(const float* __restrict__ A,
                                                const int* __restrict__ rowstart,
                                                const int* __restrict__ csrc,
                                                const float* __restrict__ cw,
                                                const float* __restrict__ dis,
                                                const float* __restrict__ bias,
                                                float* __restrict__ Y, int n) {
    int wid  = (blockIdx.x * blockDim.x + threadIdx.x) >> 5;
    int lane = threadIdx.x & 31;
    if (wid >= n) return;

    float d  = dis[wid];
    float sn = d * d;
    float2 a = *(const float2*)&A[(size_t)wid * HD + lane * 2];
    float2 acc0 = make_float2(a.x * sn, a.y * sn);
    float2 acc1 = make_float2(0.f, 0.f);

    int e  = rowstart[wid];
    int e1 = rowstart[wid + 1];

    // Unroll by 4: all four A-row loads issued before consuming (MLP=4).
    for (; e + 4 <= e1; e += 4) {
        int   s0 = csrc[e],     s1 = csrc[e + 1], s2 = csrc[e + 2], s3 = csrc[e + 3];
        float w0 = cw[e],       w1 = cw[e + 1],   w2 = cw[e + 2],   w3 = cw[e + 3];
        float2 v0 = *(const float2*)&A[(size_t)s0 * HD + lane * 2];
        float2 v1 = *(const float2*)&A[(size_t)s1 * HD + lane * 2];
        float2 v2 = *(const float2*)&A[(size_t)s2 * HD + lane * 2];
        float2 v3 = *(const float2*)&A[(size_t)s3 * HD + lane * 2];
        acc0.x = fmaf(v0.x, w0, acc0.x); acc0.y = fmaf(v0.y, w0, acc0.y);
        acc1.x = fmaf(v1.x, w1, acc1.x); acc1.y = fmaf(v1.y, w1, acc1.y);
        acc0.x = fmaf(v2.x, w2, acc0.x); acc0.y = fmaf(v2.y, w2, acc0.y);
        acc1.x = fmaf(v3.x, w3, acc1.x); acc1.y = fmaf(v3.y, w3, acc1.y);
    }
    for (; e < e1; e++) {
        int   s = csrc[e];
        float w = cw[e];
        float2 v = *(const float2*)&A[(size_t)s * HD + lane * 2];
        acc0.x = fmaf(v.x, w, acc0.x);
        acc0.y = fmaf(v.y, w, acc0.y);
    }

    float2 b = *(const float2*)&bias[lane * 2];
    float2 r;
    r.x = acc0.x + acc1.x + b.x;
    r.y = acc0.y + acc1.y + b.y;
    *(float2*)&Y[(size_t)wid * HD + lane * 2] = r;
}

// ---------------- launch ----------------
extern "C" void kernel_launch(void* const* d_in, const int* in_sizes, int n_in,
                              void* d_out, int out_size) {
    const float* x  = (const float*)d_in[0];
    const void*  ei = d_in[1];   // [2,E]; dtype sniffed on device (int32 vs int64)
    const float* W1 = (const float*)d_in[3];
    const float* b1 = (const float*)d_in[4];
    const float* W2 = (const float*)d_in[5];
    const float* b2 = (const float*)d_in[6];
    const float* W3 = (const float*)d_in[7];
    const float* b3 = (const float*)d_in[8];

    int n = in_sizes[0] / HD;   // 100000
    int e = in_sizes[1] / 2;    // 1600000

    int*   src32;    cudaGetSymbolAddress((void**)&src32, g_src32);
    int*   dst32;    cudaGetSymbolAddress((void**)&dst32, g_dst32);
    int*   cnt;      cudaGetSymbolAddress((void**)&cnt, g_cnt);
    int*   rowstart; cudaGetSymbolAddress((void**)&rowstart, g_rowstart);
    int*   cursor;   cudaGetSymbolAddress((void**)&cursor, g_cursor);
    float* dis;      cudaGetSymbolAddress((void**)&dis, g_dis);
    int*   blocksum; cudaGetSymbolAddress((void**)&blocksum, g_blocksum);
    int*   blockoff; cudaGetSymbolAddress((void**)&blockoff, g_blockoff);
    int*   csrc;     cudaGetSymbolAddress((void**)&csrc, g_csrc);
    float* cw;       cudaGetSymbolAddress((void**)&cw, g_cw);
    float* bufA;     cudaGetSymbolAddress((void**)&bufA, g_bufA);
    float* bufB;     cudaGetSymbolAddress((void**)&bufB, g_bufB);
    float* out = (float*)d_out;

    int nb_n = (n + 255) / 256;
    int nb_e = (e + 255) / 256;
    int nb_g = (n * 32 + 255) / 256;               // one warp per node
    int nb_m = (n + 63) / 64;
    int nb_s = (n + SCAN_CHUNK - 1) / SCAN_CHUNK;  // 98 scan blocks

    // ---- edge index normalization + CSR build (once per call) ----
    k_detect<<<1, 256>>>(ei);
    k_zero_int<<<nb_n, 256>>>(cnt, n);
    k_convhist<<<nb_e, 256>>>(ei, e, n, cnt);
    k_scan1<<<nb_s, SCAN_CHUNK>>>(cnt, rowstart, blocksum, dis, n);
    k_scan2<<<1, MAX_SCAN_BLOCKS>>>(blocksum, blockoff, nb_s, rowstart, n);
    k_scan3<<<nb_s, SCAN_CHUNK>>>(rowstart, cursor, blockoff, n);
    k_fill<<<nb_e, 256>>>(src32, dst32, e, n, dis, cursor, csrc, cw);

    // ---- layer 1 ----
    k_gemm<<<nb_m, 256>>>(x, W1, bufA, n, 0);
    k_gather<<<nb_g, 256>>>(bufA, rowstart, csrc, cw, dis, b1, bufB, n);
    // ---- layer 2 (ReLU fused into GEMM input load) ----
    k_gemm<<<nb_m, 256>>>(bufB, W2, bufA, n, 1);
    k_gather<<<nb_g, 256>>>(bufA, rowstart, csrc, cw, dis, b2, bufB, n);
    // ---- layer 3 ----
    k_gemm<<<nb_m, 256>>>(bufB, W3, bufA, n, 1);
    k_gather<<<nb_g, 256>>>(bufA, rowstart, csrc, cw, dis, b3, out, n);
}

// round 6
// speedup vs baseline: 1.7020x; 1.0877x over previous
#include <cuda_runtime.h>
#include <cuda_fp16.h>
#include <cstdint>

// Problem constants (shapes are fixed by the dataset).
#define NN 100000
#define EE 1600000
#define HD 64
#define SCAN_CHUNK 1024
#define MAX_SCAN_BLOCKS 128

// ---------------- scratch (device globals: allocation-free) ----------------
__device__ int    g_is64;
__device__ int    g_src32[EE];
__device__ int    g_dst32[EE];
__device__ int    g_cnt[NN];
__device__ int    g_rowstart[NN + 1];
__device__ int    g_cursor[NN];
__device__ float  g_dis[NN];
__device__ int    g_blocksum[MAX_SCAN_BLOCKS];
__device__ int    g_blockoff[MAX_SCAN_BLOCKS];
__device__ int    g_csrc[EE];
__device__ float  g_cw[EE];
__device__ __half g_bufAh[(size_t)NN * HD];   // fp16 GEMM output (gather input)
__device__ float  g_bufB[(size_t)NN * HD];    // fp32 gather output (GEMM input)

// ---------------- dtype sniff: int64 edge_index has zero high words ----------------
__global__ void k_detect(const void* ei) {
    __shared__ int nz;
    if (threadIdx.x == 0) nz = 0;
    __syncthreads();
    unsigned v = ((const unsigned*)ei)[2 * threadIdx.x + 1];
    if (v != 0) atomicOr(&nz, 1);
    __syncthreads();
    if (threadIdx.x == 0) g_is64 = (nz == 0) ? 1 : 0;
}

__global__ void k_zero_int(int* p, int n) {
    int i = blockIdx.x * blockDim.x + threadIdx.x;
    if (i < n) p[i] = 0;
}

// ---------------- convert edge_index to int32 src/dst AND histogram dst ----------------
__global__ void k_convhist(const void* ei, int e, int n, int* __restrict__ cnt) {
    int i = blockIdx.x * blockDim.x + threadIdx.x;
    if (i >= e) return;
    int s, d;
    if (g_is64) {
        const long long* p = (const long long*)ei;
        s = (int)p[i];
        d = (int)p[(size_t)e + i];
    } else {
        const int* p = (const int*)ei;
        s = p[i];
        d = p[e + i];
    }
    g_src32[i] = s;
    g_dst32[i] = d;
    if ((unsigned)d < (unsigned)n) atomicAdd(&cnt[d], 1);
}

// ---------------- 3-phase parallel scan over cnt ----------------
__global__ void __launch_bounds__(SCAN_CHUNK) k_scan1(const int* __restrict__ cnt,
                                                      int* __restrict__ rowstart,
                                                      int* __restrict__ blocksum,
                                                      float* __restrict__ dis, int n) {
    __shared__ int sh[SCAN_CHUNK];
    int t = threadIdx.x;
    int i = blockIdx.x * SCAN_CHUNK + t;
    int v = (i < n) ? cnt[i] : 0;
    if (i < n) dis[i] = rsqrtf((float)v + 1.0f);
    sh[t] = v;
    __syncthreads();
    #pragma unroll
    for (int off = 1; off < SCAN_CHUNK; off <<= 1) {
        int add = (t >= off) ? sh[t - off] : 0;
        __syncthreads();
        sh[t] += add;
        __syncthreads();
    }
    if (i < n) rowstart[i] = sh[t] - v;
    if (t == SCAN_CHUNK - 1) blocksum[blockIdx.x] = sh[SCAN_CHUNK - 1];
}

__global__ void k_scan2(const int* __restrict__ blocksum, int* __restrict__ blockoff,
                        int nb, int* __restrict__ rowstart, int n) {
    __shared__ int sh[MAX_SCAN_BLOCKS];
    int t = threadIdx.x;
    int v = (t < nb) ? blocksum[t] : 0;
    sh[t] = v;
    __syncthreads();
    #pragma unroll
    for (int off = 1; off < MAX_SCAN_BLOCKS; off <<= 1) {
        int add = (t >= off) ? sh[t - off] : 0;
        __syncthreads();
        sh[t] += add;
        __syncthreads();
    }
    if (t < nb) blockoff[t] = sh[t] - v;
    if (t == MAX_SCAN_BLOCKS - 1) rowstart[n] = sh[MAX_SCAN_BLOCKS - 1];
}

__global__ void __launch_bounds__(SCAN_CHUNK) k_scan3(int* __restrict__ rowstart,
                                                      int* __restrict__ cursor,
                                                      const int* __restrict__ blockoff, int n) {
    int i = blockIdx.x * SCAN_CHUNK + threadIdx.x;
    if (i < n) {
        int r = rowstart[i] + blockoff[blockIdx.x];
        rowstart[i] = r;
        cursor[i]   = r;
    }
}

// ---------------- CSR fill ----------------
__global__ void k_fill(const int* __restrict__ src, const int* __restrict__ dst,
                       int e, int n, const float* __restrict__ dis,
                       int* __restrict__ cursor, int* __restrict__ csrc, float* __restrict__ cw) {
    int i = blockIdx.x * blockDim.x + threadIdx.x;
    if (i < e) {
        int s = src[i];
        int d = dst[i];
        if ((unsigned)s >= (unsigned)n || (unsigned)d >= (unsigned)n) return;
        float w = dis[s] * dis[d];
        int p = atomicAdd(&cursor[d], 1);
        csrc[p] = s;
        cw[p]   = w;
    }
}

// ---------------- GEMM: Yh[n,64] = act(X)[n,64] @ W[64,64]  (fp32 math, fp16 out) ----------------
__global__ void __launch_bounds__(256) k_gemm(const float* __restrict__ X,
                                              const float* __restrict__ W,
                                              __half* __restrict__ Y, int n, int relu_in) {
    __shared__ float sW[64 * 64];
    __shared__ float sX[64 * 68];

    int t    = threadIdx.x;
    int row0 = blockIdx.x * 64;

    {
        const float4* W4  = (const float4*)W;
        float4*       sW4 = (float4*)sW;
        #pragma unroll
        for (int i = 0; i < 4; i++) sW4[t + i * 256] = W4[t + i * 256];
    }
    {
        int kc = (t & 15) * 4;
        int rl = t >> 4;
        #pragma unroll
        for (int i = 0; i < 4; i++) {
            int r  = rl + i * 16;
            int gr = row0 + r;
            float4 v = make_float4(0.f, 0.f, 0.f, 0.f);
            if (gr < n) v = *(const float4*)&X[(size_t)gr * HD + kc];
            if (relu_in) {
                v.x = fmaxf(v.x, 0.f); v.y = fmaxf(v.y, 0.f);
                v.z = fmaxf(v.z, 0.f); v.w = fmaxf(v.w, 0.f);
            }
            *(float4*)&sX[r * 68 + kc] = v;
        }
    }
    __syncthreads();

    int tx = t & 15, ty = t >> 4;
    int r0 = ty * 4, j0 = tx * 4;

    float acc[4][4];
    #pragma unroll
    for (int r = 0; r < 4; r++)
        #pragma unroll
        for (int c = 0; c < 4; c++) acc[r][c] = 0.f;

    #pragma unroll 4
    for (int k = 0; k < 64; k += 4) {
        float a[4][4];
        #pragma unroll
        for (int r = 0; r < 4; r++) {
            float4 t4 = *(const float4*)&sX[(r0 + r) * 68 + k];
            a[r][0] = t4.x; a[r][1] = t4.y; a[r][2] = t4.z; a[r][3] = t4.w;
        }
        #pragma unroll
        for (int kk = 0; kk < 4; kk++) {
            float4 w4 = *(const float4*)&sW[(k + kk) * 64 + j0];
            float wv[4] = {w4.x, w4.y, w4.z, w4.w};
            #pragma unroll
            for (int r = 0; r < 4; r++)
                #pragma unroll
                for (int c = 0; c < 4; c++)
                    acc[r][c] = fmaf(a[r][kk], wv[c], acc[r][c]);
        }
    }

    #pragma unroll
    for (int r = 0; r < 4; r++) {
        int gr = row0 + r0 + r;
        if (gr < n) {
            __half2 h0 = __floats2half2_rn(acc[r][0], acc[r][1]);
            __half2 h1 = __floats2half2_rn(acc[r][2], acc[r][3]);
            uint2 pk;
            pk.x = *(unsigned*)&h0;
            pk.y = *(unsigned*)&h1;
            *(uint2*)&Y[(size_t)gr * HD + j0] = pk;   // 8B-aligned STG.64
        }
    }
}

// ---------------- Gather: one warp per node, HALF-WARP per edge (fp16 rows) ----------------
// Y[i] = sum_{e in CSR(i)} A[src_e]*w_e  +  A[i]*dis[i]^2  +  b   (fp32 accumulate)
__global__ void __launch_bounds__(256) k_gather(const __half* __restrict__ A,
                                                const int* __restrict__ rowstart,
                                                const int* __restrict__ csrc,
                                                const float* __restrict__ cw,
                                                const float* __restrict__ dis,
                                                const float* __restrict__ bias,
                                                float* __restrict__ Y, int n) {
    int wid  = (blockIdx.x * blockDim.x + threadIdx.x) >> 5;
    int lane = threadIdx.x & 31;
    if (wid >= n) return;

    int half_id = lane >> 4;        // 0 or 1: which edge of the pair
    int col     = (lane & 15) * 4;  // 4 fp16 channels per lane (8 bytes)

    float4 acc = make_float4(0.f, 0.f, 0.f, 0.f);

    // Self-loop term (added by half 0 only; shfl-reduce sums halves).
    if (half_id == 0) {
        float d  = dis[wid];
        float sn = d * d;
        uint2 raw = *(const uint2*)&A[(size_t)wid * HD + col];
        float2 f0 = __half22float2(*(__half2*)&raw.x);
        float2 f1 = __half22float2(*(__half2*)&raw.y);
        acc.x = f0.x * sn; acc.y = f0.y * sn;
        acc.z = f1.x * sn; acc.w = f1.y * sn;
    }

    int e0 = rowstart[wid];
    int e1 = rowstart[wid + 1];

    // Each half-warp processes alternating edges: two 128B rows in flight per warp.
    for (int e = e0 + half_id; e < e1; e += 2) {
        int   s = csrc[e];
        float w = cw[e];
        uint2 raw = *(const uint2*)&A[(size_t)s * HD + col];
        float2 f0 = __half22float2(*(__half2*)&raw.x);
        float2 f1 = __half22float2(*(__half2*)&raw.y);
        acc.x = fmaf(f0.x, w, acc.x);
        acc.y = fmaf(f0.y, w, acc.y);
        acc.z = fmaf(f1.x, w, acc.z);
        acc.w = fmaf(f1.y, w, acc.w);
    }

    // Combine the two halves.
    acc.x += __shfl_xor_sync(0xffffffffu, acc.x, 16);
    acc.y += __shfl_xor_sync(0xffffffffu, acc.y, 16);
    acc.z += __shfl_xor_sync(0xffffffffu, acc.z, 16);
    acc.w += __shfl_xor_sync(0xffffffffu, acc.w, 16);

    if (half_id == 0) {
        float4 b = *(const float4*)&bias[col];
        acc.x += b.x; acc.y += b.y; acc.z += b.z; acc.w += b.w;
        *(float4*)&Y[(size_t)wid * HD + col] = acc;
    }
}

// ---------------- launch ----------------
extern "C" void kernel_launch(void* const* d_in, const int* in_sizes, int n_in,
                              void* d_out, int out_size) {
    const float* x  = (const float*)d_in[0];
    const void*  ei = d_in[1];   // [2,E]; dtype sniffed on device (int32 vs int64)
    const float* W1 = (const float*)d_in[3];
    const float* b1 = (const float*)d_in[4];
    const float* W2 = (const float*)d_in[5];
    const float* b2 = (const float*)d_in[6];
    const float* W3 = (const float*)d_in[7];
    const float* b3 = (const float*)d_in[8];

    int n = in_sizes[0] / HD;   // 100000
    int e = in_sizes[1] / 2;    // 1600000

    int*    src32;    cudaGetSymbolAddress((void**)&src32, g_src32);
    int*    dst32;    cudaGetSymbolAddress((void**)&dst32, g_dst32);
    int*    cnt;      cudaGetSymbolAddress((void**)&cnt, g_cnt);
    int*    rowstart; cudaGetSymbolAddress((void**)&rowstart, g_rowstart);
    int*    cursor;   cudaGetSymbolAddress((void**)&cursor, g_cursor);
    float*  dis;      cudaGetSymbolAddress((void**)&dis, g_dis);
    int*    blocksum; cudaGetSymbolAddress((void**)&blocksum, g_blocksum);
    int*    blockoff; cudaGetSymbolAddress((void**)&blockoff, g_blockoff);
    int*    csrc;     cudaGetSymbolAddress((void**)&csrc, g_csrc);
    float*  cw;       cudaGetSymbolAddress((void**)&cw, g_cw);
    __half* bufAh;    cudaGetSymbolAddress((void**)&bufAh, g_bufAh);
    float*  bufB;     cudaGetSymbolAddress((void**)&bufB, g_bufB);
    float*  out = (float*)d_out;

    int nb_n = (n + 255) / 256;
    int nb_e = (e + 255) / 256;
    int nb_g = (n * 32 + 255) / 256;               // one warp per node
    int nb_m = (n + 63) / 64;
    int nb_s = (n + SCAN_CHUNK - 1) / SCAN_CHUNK;  // 98 scan blocks

    // ---- edge index normalization + CSR build (once per call) ----
    k_detect<<<1, 256>>>(ei);
    k_zero_int<<<nb_n, 256>>>(cnt, n);
    k_convhist<<<nb_e, 256>>>(ei, e, n, cnt);
    k_scan1<<<nb_s, SCAN_CHUNK>>>(cnt, rowstart, blocksum, dis, n);
    k_scan2<<<1, MAX_SCAN_BLOCKS>>>(blocksum, blockoff, nb_s, rowstart, n);
    k_scan3<<<nb_s, SCAN_CHUNK>>>(rowstart, cursor, blockoff, n);
    k_fill<<<nb_e, 256>>>(src32, dst32, e, n, dis, cursor, csrc, cw);

    // ---- layer 1 ----
    k_gemm<<<nb_m, 256>>>(x, W1, bufAh, n, 0);
    k_gather<<<nb_g, 256>>>(bufAh, rowstart, csrc, cw, dis, b1, bufB, n);
    // ---- layer 2 (ReLU fused into GEMM input load) ----
    k_gemm<<<nb_m, 256>>>(bufB, W2, bufAh, n, 1);
    k_gather<<<nb_g, 256>>>(bufAh, rowstart, csrc, cw, dis, b2, bufB, n);
    // ---- layer 3 ----
    k_gemm<<<nb_m, 256>>>(bufB, W3, bufAh, n, 1);
    k_gather<<<nb_g, 256>>>(bufAh, rowstart, csrc, cw, dis, b3, out, n);
}

// round 9
// speedup vs baseline: 1.8657x; 1.0962x over previous
#include <cuda_runtime.h>
#include <cuda_fp16.h>
#include <cstdint>

// Problem constants (shapes are fixed by the dataset).
#define NN 100000
#define EE 1600000
#define HD 64
#define SCAN_CHUNK 1024
#define MAX_SCAN_BLOCKS 128
#define GROWS 64    // GEMM rows per block (64*68*4 + 64*68*4 = 34816B smem < 48KB)

// ---------------- scratch (device globals: allocation-free) ----------------
__device__ int    g_is64;
__device__ int    g_src32[EE];
__device__ int    g_dst32[EE];
__device__ int    g_cnt[NN];
__device__ int    g_rowstart[NN + 1];
__device__ int    g_cursor[NN];
__device__ float  g_dis[NN];
__device__ int    g_blocksum[MAX_SCAN_BLOCKS];
__device__ int    g_blockoff[MAX_SCAN_BLOCKS];
__device__ int    g_csrc[EE];
__device__ float  g_cw[EE];
__device__ __half g_bufAh[(size_t)NN * HD];   // fp16 GEMM output (gather input)
__device__ float  g_bufB[(size_t)NN * HD];    // fp32 gather output (GEMM input)

// ---------------- dtype sniff: int64 edge_index has zero high words ----------------
__global__ void k_detect(const void* ei) {
    __shared__ int nz;
    if (threadIdx.x == 0) nz = 0;
    __syncthreads();
    unsigned v = ((const unsigned*)ei)[2 * threadIdx.x + 1];
    if (v != 0) atomicOr(&nz, 1);
    __syncthreads();
    if (threadIdx.x == 0) g_is64 = (nz == 0) ? 1 : 0;
}

__global__ void k_zero_int(int* p, int n) {
    int i = blockIdx.x * blockDim.x + threadIdx.x;
    if (i < n) p[i] = 0;
}

// ---------------- convert edge_index to int32 src/dst AND histogram dst ----------------
__global__ void k_convhist(const void* ei, int e, int n, int* __restrict__ cnt) {
    int i = blockIdx.x * blockDim.x + threadIdx.x;
    if (i >= e) return;
    int s, d;
    if (g_is64) {
        const long long* p = (const long long*)ei;
        s = (int)p[i];
        d = (int)p[(size_t)e + i];
    } else {
        const int* p = (const int*)ei;
        s = p[i];
        d = p[e + i];
    }
    g_src32[i] = s;
    g_dst32[i] = d;
    if ((unsigned)d < (unsigned)n) atomicAdd(&cnt[d], 1);
}

// ---------------- 3-phase parallel scan over cnt ----------------
__global__ void __launch_bounds__(SCAN_CHUNK) k_scan1(const int* __restrict__ cnt,
                                                      int* __restrict__ rowstart,
                                                      int* __restrict__ blocksum,
                                                      float* __restrict__ dis, int n) {
    __shared__ int sh[SCAN_CHUNK];
    int t = threadIdx.x;
    int i = blockIdx.x * SCAN_CHUNK + t;
    int v = (i < n) ? cnt[i] : 0;
    if (i < n) dis[i] = rsqrtf((float)v + 1.0f);
    sh[t] = v;
    __syncthreads();
    #pragma unroll
    for (int off = 1; off < SCAN_CHUNK; off <<= 1) {
        int add = (t >= off) ? sh[t - off] : 0;
        __syncthreads();
        sh[t] += add;
        __syncthreads();
    }
    if (i < n) rowstart[i] = sh[t] - v;
    if (t == SCAN_CHUNK - 1) blocksum[blockIdx.x] = sh[SCAN_CHUNK - 1];
}

__global__ void k_scan2(const int* __restrict__ blocksum, int* __restrict__ blockoff,
                        int nb, int* __restrict__ rowstart, int n) {
    __shared__ int sh[MAX_SCAN_BLOCKS];
    int t = threadIdx.x;
    int v = (t < nb) ? blocksum[t] : 0;
    sh[t] = v;
    __syncthreads();
    #pragma unroll
    for (int off = 1; off < MAX_SCAN_BLOCKS; off <<= 1) {
        int add = (t >= off) ? sh[t - off] : 0;
        __syncthreads();
        sh[t] += add;
        __syncthreads();
    }
    if (t < nb) blockoff[t] = sh[t] - v;
    if (t == MAX_SCAN_BLOCKS - 1) rowstart[n] = sh[MAX_SCAN_BLOCKS - 1];
}

__global__ void __launch_bounds__(SCAN_CHUNK) k_scan3(int* __restrict__ rowstart,
                                                      int* __restrict__ cursor,
                                                      const int* __restrict__ blockoff, int n) {
    int i = blockIdx.x * SCAN_CHUNK + threadIdx.x;
    if (i < n) {
        int r = rowstart[i] + blockoff[blockIdx.x];
        rowstart[i] = r;
        cursor[i]   = r;
    }
}

// ---------------- CSR fill ----------------
__global__ void k_fill(const int* __restrict__ src, const int* __restrict__ dst,
                       int e, int n, const float* __restrict__ dis,
                       int* __restrict__ cursor, int* __restrict__ csrc, float* __restrict__ cw) {
    int i = blockIdx.x * blockDim.x + threadIdx.x;
    if (i < e) {
        int s = src[i];
        int d = dst[i];
        if ((unsigned)s >= (unsigned)n || (unsigned)d >= (unsigned)n) return;
        float w = dis[s] * dis[d];
        int p = atomicAdd(&cursor[d], 1);
        csrc[p] = s;
        cw[p]   = w;
    }
}

// ---------------- tf32 helpers ----------------
// cvt.rna.tf32.f32 requires a .b32 destination register: return the bit pattern.
__device__ __forceinline__ float to_tf32(float x) {
    unsigned r;
    asm("cvt.rna.tf32.f32 %0, %1;" : "=r"(r) : "f"(x));
    return __uint_as_float(r);
}

__device__ __forceinline__ void mma_tf32(float* c, unsigned a0, unsigned a1,
                                         unsigned a2, unsigned a3,
                                         unsigned b0, unsigned b1) {
    asm volatile(
        "mma.sync.aligned.m16n8k8.row.col.f32.tf32.tf32.f32 "
        "{%0,%1,%2,%3}, {%4,%5,%6,%7}, {%8,%9}, {%0,%1,%2,%3};"
        : "+f"(c[0]), "+f"(c[1]), "+f"(c[2]), "+f"(c[3])
        : "r"(a0), "r"(a1), "r"(a2), "r"(a3), "r"(b0), "r"(b1));
}

// ---------------- GEMM (tf32 tensor core): Yh[n,64] = act(X)[n,64] @ W[64,64] ----------------
// 128 threads = 4 warps; block tile 64 rows; warp w -> m16 stripe [w*16, w*16+16), full n=64.
// tf32 fragments per PTX m16n8k8 layout: g = lane>>2, tq = lane&3.
__global__ void __launch_bounds__(128) k_gemm_tc(const float* __restrict__ X,
                                                 const float* __restrict__ W,
                                                 __half* __restrict__ Y, int n, int relu_in) {
    __shared__ float sA[GROWS * 68];   // X tile (tf32 bits), pad 68 for conflict-free frags
    __shared__ float sB[64 * 68];      // W (tf32 bits), [k][n]

    int t    = threadIdx.x;
    int row0 = blockIdx.x * GROWS;

    // Load W (4096 floats) coalesced float4, convert to tf32 on store.
    #pragma unroll
    for (int i = 0; i < 8; i++) {
        int idx = i * 512 + t * 4;
        float4 v = *(const float4*)&W[idx];
        int k  = idx >> 6;
        int nn = idx & 63;
        sB[k * 68 + nn + 0] = to_tf32(v.x);
        sB[k * 68 + nn + 1] = to_tf32(v.y);
        sB[k * 68 + nn + 2] = to_tf32(v.z);
        sB[k * 68 + nn + 3] = to_tf32(v.w);
    }
    // Load X tile (64 rows x 64 cols), optional ReLU, tf32 convert, zero-pad OOB.
    {
        int kc = (t & 15) * 4;
        int rl = t >> 4;            // 0..7
        #pragma unroll
        for (int i = 0; i < 8; i++) {
            int r  = rl + i * 8;
            int gr = row0 + r;
            float4 v = make_float4(0.f, 0.f, 0.f, 0.f);
            if (gr < n) v = *(const float4*)&X[(size_t)gr * HD + kc];
            if (relu_in) {
                v.x = fmaxf(v.x, 0.f); v.y = fmaxf(v.y, 0.f);
                v.z = fmaxf(v.z, 0.f); v.w = fmaxf(v.w, 0.f);
            }
            sA[r * 68 + kc + 0] = to_tf32(v.x);
            sA[r * 68 + kc + 1] = to_tf32(v.y);
            sA[r * 68 + kc + 2] = to_tf32(v.z);
            sA[r * 68 + kc + 3] = to_tf32(v.w);
        }
    }
    __syncthreads();

    int warp = t >> 5, lane = t & 31;
    int g  = lane >> 2;     // group id 0..7
    int tq = lane & 3;      // thread-in-group 0..3
    int mrow = warp * 16;

    float c[8][4];
    #pragma unroll
    for (int nf = 0; nf < 8; nf++)
        #pragma unroll
        for (int j = 0; j < 4; j++) c[nf][j] = 0.f;

    #pragma unroll
    for (int kk = 0; kk < 8; kk++) {
        int k0 = kk * 8;
        // A fragment (m16 k8): a0=A[g][tq], a1=A[g+8][tq], a2=A[g][tq+4], a3=A[g+8][tq+4]
        unsigned a0 = __float_as_uint(sA[(mrow + g)     * 68 + k0 + tq]);
        unsigned a1 = __float_as_uint(sA[(mrow + g + 8) * 68 + k0 + tq]);
        unsigned a2 = __float_as_uint(sA[(mrow + g)     * 68 + k0 + tq + 4]);
        unsigned a3 = __float_as_uint(sA[(mrow + g + 8) * 68 + k0 + tq + 4]);
        #pragma unroll
        for (int nf = 0; nf < 8; nf++) {
            // B fragment (k8 n8): b0=B[tq][g], b1=B[tq+4][g]
            unsigned b0 = __float_as_uint(sB[(k0 + tq)     * 68 + nf * 8 + g]);
            unsigned b1 = __float_as_uint(sB[(k0 + tq + 4) * 68 + nf * 8 + g]);
            mma_tf32(c[nf], a0, a1, a2, a3, b0, b1);
        }
    }

    // Epilogue: C (m16 n8): c0=C[g][2tq], c1=C[g][2tq+1], c2=C[g+8][2tq], c3=C[g+8][2tq+1]
    int gr0 = row0 + mrow + g;
    int gr1 = gr0 + 8;
    #pragma unroll
    for (int nf = 0; nf < 8; nf++) {
        int colb = nf * 8 + 2 * tq;
        if (gr0 < n) {
            __half2 h = __floats2half2_rn(c[nf][0], c[nf][1]);
            *(__half2*)&Y[(size_t)gr0 * HD + colb] = h;
        }
        if (gr1 < n) {
            __half2 h = __floats2half2_rn(c[nf][2], c[nf][3]);
            *(__half2*)&Y[(size_t)gr1 * HD + colb] = h;
        }
    }
}

// ---------------- Gather: one warp per node, HALF-WARP per edge (fp16 rows) ----------------
// Y[i] = sum_{e in CSR(i)} A[src_e]*w_e  +  A[i]*dis[i]^2  +  b   (fp32 accumulate)
__global__ void __launch_bounds__(256) k_gather(const __half* __restrict__ A,
                                                const int* __restrict__ rowstart,
                                                const int* __restrict__ csrc,
                                                const float* __restrict__ cw,
                                                const float* __restrict__ dis,
                                                const float* __restrict__ bias,
                                                float* __restrict__ Y, int n) {
    int wid  = (blockIdx.x * blockDim.x + threadIdx.x) >> 5;
    int lane = threadIdx.x & 31;
    if (wid >= n) return;

    int half_id = lane >> 4;        // 0 or 1: which edge of the pair
    int col     = (lane & 15) * 4;  // 4 fp16 channels per lane (8 bytes)

    float4 acc = make_float4(0.f, 0.f, 0.f, 0.f);

    // Self-loop term (added by half 0 only; shfl-reduce sums halves).
    if (half_id == 0) {
        float d  = dis[wid];
        float sn = d * d;
        uint2 raw = *(const uint2*)&A[(size_t)wid * HD + col];
        float2 f0 = __half22float2(*(__half2*)&raw.x);
        float2 f1 = __half22float2(*(__half2*)&raw.y);
        acc.x = f0.x * sn; acc.y = f0.y * sn;
        acc.z = f1.x * sn; acc.w = f1.y * sn;
    }

    int e0 = rowstart[wid];
    int e1 = rowstart[wid + 1];

    for (int e = e0 + half_id; e < e1; e += 2) {
        int   s = csrc[e];
        float w = cw[e];
        uint2 raw = *(const uint2*)&A[(size_t)s * HD + col];
        float2 f0 = __half22float2(*(__half2*)&raw.x);
        float2 f1 = __half22float2(*(__half2*)&raw.y);
        acc.x = fmaf(f0.x, w, acc.x);
        acc.y = fmaf(f0.y, w, acc.y);
        acc.z = fmaf(f1.x, w, acc.z);
        acc.w = fmaf(f1.y, w, acc.w);
    }

    acc.x += __shfl_xor_sync(0xffffffffu, acc.x, 16);
    acc.y += __shfl_xor_sync(0xffffffffu, acc.y, 16);
    acc.z += __shfl_xor_sync(0xffffffffu, acc.z, 16);
    acc.w += __shfl_xor_sync(0xffffffffu, acc.w, 16);

    if (half_id == 0) {
        float4 b = *(const float4*)&bias[col];
        acc.x += b.x; acc.y += b.y; acc.z += b.z; acc.w += b.w;
        *(float4*)&Y[(size_t)wid * HD + col] = acc;
    }
}

// ---------------- launch ----------------
extern "C" void kernel_launch(void* const* d_in, const int* in_sizes, int n_in,
                              void* d_out, int out_size) {
    const float* x  = (const float*)d_in[0];
    const void*  ei = d_in[1];   // [2,E]; dtype sniffed on device (int32 vs int64)
    const float* W1 = (const float*)d_in[3];
    const float* b1 = (const float*)d_in[4];
    const float* W2 = (const float*)d_in[5];
    const float* b2 = (const float*)d_in[6];
    const float* W3 = (const float*)d_in[7];
    const float* b3 = (const float*)d_in[8];

    int n = in_sizes[0] / HD;   // 100000
    int e = in_sizes[1] / 2;    // 1600000

    int*    src32;    cudaGetSymbolAddress((void**)&src32, g_src32);
    int*    dst32;    cudaGetSymbolAddress((void**)&dst32, g_dst32);
    int*    cnt;      cudaGetSymbolAddress((void**)&cnt, g_cnt);
    int*    rowstart; cudaGetSymbolAddress((void**)&rowstart, g_rowstart);
    int*    cursor;   cudaGetSymbolAddress((void**)&cursor, g_cursor);
    float*  dis;      cudaGetSymbolAddress((void**)&dis, g_dis);
    int*    blocksum; cudaGetSymbolAddress((void**)&blocksum, g_blocksum);
    int*    blockoff; cudaGetSymbolAddress((void**)&blockoff, g_blockoff);
    int*    csrc;     cudaGetSymbolAddress((void**)&csrc, g_csrc);
    float*  cw;       cudaGetSymbolAddress((void**)&cw, g_cw);
    __half* bufAh;    cudaGetSymbolAddress((void**)&bufAh, g_bufAh);
    float*  bufB;     cudaGetSymbolAddress((void**)&bufB, g_bufB);
    float*  out = (float*)d_out;

    int nb_n = (n + 255) / 256;
    int nb_e = (e + 255) / 256;
    int nb_g = (n * 32 + 255) / 256;               // one warp per node
    int nb_m = (n + GROWS - 1) / GROWS;            // 64-row GEMM tiles
    int nb_s = (n + SCAN_CHUNK - 1) / SCAN_CHUNK;  // 98 scan blocks

    // ---- edge index normalization + CSR build (once per call) ----
    k_detect<<<1, 256>>>(ei);
    k_zero_int<<<nb_n, 256>>>(cnt, n);
    k_convhist<<<nb_e, 256>>>(ei, e, n, cnt);
    k_scan1<<<nb_s, SCAN_CHUNK>>>(cnt, rowstart, blocksum, dis, n);
    k_scan2<<<1, MAX_SCAN_BLOCKS>>>(blocksum, blockoff, nb_s, rowstart, n);
    k_scan3<<<nb_s, SCAN_CHUNK>>>(rowstart, cursor, blockoff, n);
    k_fill<<<nb_e, 256>>>(src32, dst32, e, n, dis, cursor, csrc, cw);

    // ---- layer 1 ----
    k_gemm_tc<<<nb_m, 128>>>(x, W1, bufAh, n, 0);
    k_gather<<<nb_g, 256>>>(bufAh, rowstart, csrc, cw, dis, b1, bufB, n);
    // ---- layer 2 (ReLU fused into GEMM input load) ----
    k_gemm_tc<<<nb_m, 128>>>(bufB, W2, bufAh, n, 1);
    k_gather<<<nb_g, 256>>>(bufAh, rowstart, csrc, cw, dis, b2, bufB, n);
    // ---- layer 3 ----
    k_gemm_tc<<<nb_m, 128>>>(bufB, W3, bufAh, n, 1);
    k_gather<<<nb_g, 256>>>(bufAh, rowstart, csrc, cw, dis, b3, out, n);
}